// round 5
// baseline (speedup 1.0000x reference)
#include <cuda_runtime.h>
#include <cuda_fp16.h>
#include <math.h>

#define DIM    1024
#define PAR    8
#define NN     255          // nodes per tree
#define WIDTH  2040         // PAR * NN
#define DEPTH  7
#define NSTEP  (DEPTH + 1)  // 8 visited nodes per tree
#define NACT   (PAR * NSTEP) // 64 active nodes per row
#define MAXB   8192          // max rows (4*2048)

// Static scratch (no dynamic allocation allowed):
__device__ __half g_WoutT_h[WIDTH * DIM];        // transposed W_out, fp16 (4.2MB)
__device__ float  g_act[MAXB * NACT];            // stage-1 activations (2MB)
__device__ int    g_idx[MAXB * NACT];            // stage-1 node indices (2MB)

// ---------------------------------------------------------------------------
// Kernel 1: transpose W_out [DIM, WIDTH] -> g_WoutT_h [WIDTH, DIM], fp32->fp16
// ---------------------------------------------------------------------------
__global__ __launch_bounds__(1024) void transpose_wout(const float* __restrict__ Wout) {
    __shared__ float tile[32][33];
    int wcol = blockIdx.x * 32 + threadIdx.x;  // width index (0..2039)
    int drow = blockIdx.y * 32 + threadIdx.y;  // dim index (0..1023)
    if (wcol < WIDTH) tile[threadIdx.y][threadIdx.x] = Wout[drow * WIDTH + wcol];
    __syncthreads();
    int od = blockIdx.y * 32 + threadIdx.x;    // dim (always < 1024)
    int ow = blockIdx.x * 32 + threadIdx.y;    // width
    if (ow < WIDTH)
        g_WoutT_h[(size_t)ow * DIM + od] = __float2half_rn(tile[threadIdx.x][threadIdx.y]);
}

// ---------------------------------------------------------------------------
// Kernel 2: stage 1 — tree descent. One block per row, one warp per tree.
// Decisions in exact fp32 (identical to reference). Writes (act, node) pairs.
// ---------------------------------------------------------------------------
__global__ __launch_bounds__(256) void fff_stage1(
    const float* __restrict__ x,
    const float* __restrict__ Win,
    const float* __restrict__ bin)
{
    __shared__ float4 sx[DIM / 4];   // this row's input, 4KB

    const int row  = blockIdx.x;
    const int tid  = threadIdx.x;
    const int warp = tid >> 5;
    const int lane = tid & 31;

    sx[tid] = ((const float4*)(x + (size_t)row * DIM))[tid];
    __syncthreads();

    int cur = 0;  // node index within this tree (0..254)
    #pragma unroll 1
    for (int step = 0; step < NSTEP; ++step) {
        const int wrow = warp * NN + cur;               // global width index
        const float4* __restrict__ Wr =
            (const float4*)(Win + (size_t)wrow * DIM);
        float sum = 0.f;
        #pragma unroll
        for (int k = 0; k < 8; ++k) {                   // 32 floats / lane
            const float4 wv = Wr[lane + 32 * k];
            const float4 xv = sx[lane + 32 * k];
            sum += wv.x * xv.x + wv.y * xv.y + wv.z * xv.z + wv.w * xv.w;
        }
        #pragma unroll
        for (int off = 16; off; off >>= 1)              // butterfly reduce
            sum += __shfl_xor_sync(0xffffffffu, sum, off);
        const float logit = sum + __ldg(bin + wrow);
        if (lane == 0) {
            const int o = row * NACT + warp * NSTEP + step;
            g_act[o] = logit / (1.f + expf(-logit));    // silu
            g_idx[o] = wrow;
        }
        cur = 2 * cur + 1 + (logit > 0.f ? 1 : 0);
    }
}

// ---------------------------------------------------------------------------
// Kernel 3: stage 2 — out[row] = sum_i act_i * W_outT[idx_i, :] (fp16 weights,
// fp32 accumulate). One block per row, thread t owns output dims 4t..4t+3.
// ---------------------------------------------------------------------------
__global__ __launch_bounds__(256) void fff_stage2(float* __restrict__ out)
{
    __shared__ float s_a[NACT];
    __shared__ int   s_n[NACT];

    const int row = blockIdx.x;
    const int tid = threadIdx.x;

    if (tid < NACT) {
        s_a[tid] = g_act[row * NACT + tid];
        s_n[tid] = g_idx[row * NACT + tid];
    }
    __syncthreads();

    float ax = 0.f, ay = 0.f, az = 0.f, aw = 0.f;
    #pragma unroll 8
    for (int i = 0; i < NACT; ++i) {
        const float a = s_a[i];
        const uint2 u = *((const uint2*)(g_WoutT_h + (size_t)s_n[i] * DIM) + tid);
        const __half2 h0 = *(const __half2*)&u.x;
        const __half2 h1 = *(const __half2*)&u.y;
        const float2 f0 = __half22float2(h0);
        const float2 f1 = __half22float2(h1);
        ax += a * f0.x;
        ay += a * f0.y;
        az += a * f1.x;
        aw += a * f1.y;
    }
    float4 r; r.x = ax; r.y = ay; r.z = az; r.w = aw;
    ((float4*)(out + (size_t)row * DIM))[tid] = r;
}

// ---------------------------------------------------------------------------
extern "C" void kernel_launch(void* const* d_in, const int* in_sizes, int n_in,
                              void* d_out, int out_size) {
    const float* oldx  = (const float*)d_in[0];   // [4,2048,1024] f32
    const float* W_in  = (const float*)d_in[1];   // [2040,1024] f32
    const float* b_in  = (const float*)d_in[2];   // [2040] f32
    const float* W_out = (const float*)d_in[3];   // [1024,2040] f32
    float* out = (float*)d_out;

    const int B = in_sizes[0] / DIM;              // 8192 rows

    dim3 tgrid((WIDTH + 31) / 32, DIM / 32);
    transpose_wout<<<tgrid, dim3(32, 32)>>>(W_out);

    fff_stage1<<<B, 256>>>(oldx, W_in, b_in);
    fff_stage2<<<B, 256>>>(out);
}

// round 8
// speedup vs baseline: 1.1611x; 1.1611x over previous
#include <cuda_runtime.h>
#include <cuda_fp16.h>
#include <math.h>

#define DIM    1024
#define PAR    8
#define NN     255          // nodes per tree
#define WIDTH  2040         // PAR * NN
#define DEPTH  7
#define NSTEP  (DEPTH + 1)  // 8 visited nodes per tree
#define NACT   (PAR * NSTEP) // 64 active nodes per row
#define MAXB   8192          // max rows (4*2048)

// Static scratch (no dynamic allocation allowed):
__device__ __half g_WoutT_h[WIDTH * DIM];        // transposed W_out, fp16 (4.2MB)
__device__ float  g_act[MAXB * NACT];            // stage-1 activations (2MB)
__device__ int    g_leaf[MAXB * PAR];            // depth-7 leaf per (row,tree) (256KB)

// ---------------------------------------------------------------------------
// Kernel 1: transpose W_out [DIM, WIDTH] -> g_WoutT_h [WIDTH, DIM], fp32->fp16.
// 32x32 tiles, 256 threads, half-converted in smem.
// ---------------------------------------------------------------------------
__global__ __launch_bounds__(256) void transpose_wout(const float* __restrict__ Wout) {
    __shared__ __half tile[32][33];
    const int tx = threadIdx.x, ty = threadIdx.y;
    const int w0 = blockIdx.x * 32, d0 = blockIdx.y * 32;
    const int w  = w0 + tx;
    #pragma unroll
    for (int k = 0; k < 4; ++k) {
        const int d = d0 + ty + 8 * k;
        if (w < WIDTH)
            tile[ty + 8 * k][tx] = __float2half_rn(Wout[(size_t)d * WIDTH + w]);
    }
    __syncthreads();
    #pragma unroll
    for (int k = 0; k < 4; ++k) {
        const int ww = w0 + ty + 8 * k;
        if (ww < WIDTH)
            g_WoutT_h[(size_t)ww * DIM + d0 + tx] = tile[tx][ty + 8 * k];
    }
}

// ---------------------------------------------------------------------------
// Kernel 2: stage 1 — tree descent. One block per row, one warp per tree.
// Fully unrolled over the 8 steps so the lane's x slice (32 floats) and the
// 8 activations live in REGISTERS (no per-step x traffic on the L1 port).
// Decisions in exact fp32 (identical to reference).
// ---------------------------------------------------------------------------
__global__ __launch_bounds__(256) void fff_stage1(
    const float* __restrict__ x,
    const float* __restrict__ Win,
    const float* __restrict__ bin)
{
    const int row  = blockIdx.x;
    const int warp = threadIdx.x >> 5;
    const int lane = threadIdx.x & 31;

    // Lane's fixed slice of x: elements 4*(lane+32k)..+3, k=0..7 (32 floats).
    const float4* __restrict__ xg = (const float4*)(x + (size_t)row * DIM);
    float4 xr[8];
    #pragma unroll
    for (int k = 0; k < 8; ++k) xr[k] = __ldg(xg + lane + 32 * k);

    float act[NSTEP];
    int cur = 0;  // node index within this tree (0..254)

    #pragma unroll
    for (int step = 0; step < NSTEP; ++step) {
        const int wrow = warp * NN + cur;               // global width index
        const float4* __restrict__ Wr =
            (const float4*)(Win + (size_t)wrow * DIM);
        float s0 = 0.f, s1 = 0.f;
        #pragma unroll
        for (int k = 0; k < 8; ++k) {                   // 32 floats / lane
            const float4 wv = __ldg(Wr + lane + 32 * k);
            s0 += wv.x * xr[k].x + wv.y * xr[k].y;
            s1 += wv.z * xr[k].z + wv.w * xr[k].w;
        }
        float sum = s0 + s1;
        #pragma unroll
        for (int off = 16; off; off >>= 1)              // butterfly reduce
            sum += __shfl_xor_sync(0xffffffffu, sum, off);
        const float logit = sum + __ldg(bin + wrow);
        act[step] = logit / (1.f + expf(-logit));       // silu
        cur = 2 * cur + 1 + (logit > 0.f ? 1 : 0);
    }

    if (lane == 0) {
        float4* ap = (float4*)(g_act + (size_t)row * NACT + warp * NSTEP);
        float4 a0; a0.x = act[0]; a0.y = act[1]; a0.z = act[2]; a0.w = act[3];
        float4 a1; a1.x = act[4]; a1.y = act[5]; a1.z = act[6]; a1.w = act[7];
        ap[0] = a0;
        ap[1] = a1;
        g_leaf[row * PAR + warp] = (cur - 1) >> 1;      // depth-7 node (127..254)
    }
}

// ---------------------------------------------------------------------------
// Kernel 3: stage 2 — out[row] = sum_i act_i * W_outT[node_i, :].
// fp16 weights, fp32 accumulate. 128 threads; thread t owns dims 8t..8t+7
// (one uint4 = 8 halves per node row). Node indices reconstructed from leaf.
// ---------------------------------------------------------------------------
__global__ __launch_bounds__(128) void fff_stage2(float* __restrict__ out)
{
    __shared__ float s_a[NACT];
    __shared__ int   s_w[NACT];

    const int row = blockIdx.x;
    const int tid = threadIdx.x;

    if (tid < NACT) {
        s_a[tid] = g_act[(size_t)row * NACT + tid];
        const int tree = tid >> 3;
        const int step = tid & 7;
        const int leaf = g_leaf[row * PAR + tree];      // heap idx at depth 7
        s_w[tid] = tree * NN + (((leaf + 1) >> (7 - step)) - 1);
    }
    __syncthreads();

    float acc[8];
    #pragma unroll
    for (int j = 0; j < 8; ++j) acc[j] = 0.f;

    #pragma unroll 8
    for (int i = 0; i < NACT; ++i) {
        const float a = s_a[i];
        const uint4 u = *((const uint4*)(g_WoutT_h + (size_t)s_w[i] * DIM) + tid);
        const __half2* h = (const __half2*)&u;
        #pragma unroll
        for (int j = 0; j < 4; ++j) {
            const float2 f = __half22float2(h[j]);
            acc[2 * j]     += a * f.x;
            acc[2 * j + 1] += a * f.y;
        }
    }

    float4* op = (float4*)(out + (size_t)row * DIM) + 2 * tid;
    float4 r0; r0.x = acc[0]; r0.y = acc[1]; r0.z = acc[2]; r0.w = acc[3];
    float4 r1; r1.x = acc[4]; r1.y = acc[5]; r1.z = acc[6]; r1.w = acc[7];
    op[0] = r0;
    op[1] = r1;
}

// ---------------------------------------------------------------------------
extern "C" void kernel_launch(void* const* d_in, const int* in_sizes, int n_in,
                              void* d_out, int out_size) {
    const float* oldx  = (const float*)d_in[0];   // [4,2048,1024] f32
    const float* W_in  = (const float*)d_in[1];   // [2040,1024] f32
    const float* b_in  = (const float*)d_in[2];   // [2040] f32
    const float* W_out = (const float*)d_in[3];   // [1024,2040] f32
    float* out = (float*)d_out;

    const int B = in_sizes[0] / DIM;              // 8192 rows

    transpose_wout<<<dim3((WIDTH + 31) / 32, DIM / 32), dim3(32, 8)>>>(W_out);
    fff_stage1<<<B, 256>>>(oldx, W_in, b_in);
    fff_stage2<<<B, 128>>>(out);
}

// round 10
// speedup vs baseline: 1.2909x; 1.1118x over previous
#include <cuda_runtime.h>
#include <cuda_fp16.h>
#include <math.h>

#define DIM    1024
#define PAR    8
#define NN     255          // nodes per tree
#define WIDTH  2040         // PAR * NN
#define DEPTH  7
#define NSTEP  (DEPTH + 1)  // 8 visited nodes per tree
#define NACT   (PAR * NSTEP) // 64 active nodes per row
#define MAXB   8192          // max rows (4*2048)

// Static scratch (no dynamic allocation allowed):
__device__ __half g_WoutT_h[WIDTH * DIM];        // transposed W_out, fp16 (4.2MB)
__device__ float  g_act[MAXB * NACT];            // stage-1 activations (2MB)
__device__ int    g_leaf[MAXB * PAR];            // depth-7 leaf per (row,tree)

// ---------------------------------------------------------------------------
// Kernel 1: transpose W_out [DIM, WIDTH] -> g_WoutT_h [WIDTH, DIM], fp32->fp16.
// ---------------------------------------------------------------------------
__global__ __launch_bounds__(256) void transpose_wout(const float* __restrict__ Wout) {
    __shared__ __half tile[32][33];
    const int tx = threadIdx.x, ty = threadIdx.y;
    const int w0 = blockIdx.x * 32, d0 = blockIdx.y * 32;
    const int w  = w0 + tx;
    #pragma unroll
    for (int k = 0; k < 4; ++k) {
        const int d = d0 + ty + 8 * k;
        if (w < WIDTH)
            tile[ty + 8 * k][tx] = __float2half_rn(Wout[(size_t)d * WIDTH + w]);
    }
    __syncthreads();
    #pragma unroll
    for (int k = 0; k < 4; ++k) {
        const int ww = w0 + ty + 8 * k;
        if (ww < WIDTH)
            g_WoutT_h[(size_t)ww * DIM + d0 + tx] = tile[tx][ty + 8 * k];
    }
}

// ---------------------------------------------------------------------------
// Kernel 2: stage 1 — tree descent. 128 threads per row; each of the 4 warps
// drives TWO trees interleaved (ILP-2 chains sharing one register-resident
// x slice). Decisions in exact fp32 (identical to reference).
// ---------------------------------------------------------------------------
__global__ __launch_bounds__(128, 5) void fff_stage1(
    const float* __restrict__ x,
    const float* __restrict__ Win,
    const float* __restrict__ bin)
{
    const int row  = blockIdx.x;
    const int warp = threadIdx.x >> 5;   // 0..3
    const int lane = threadIdx.x & 31;
    const int t0   = warp;               // first tree
    const int t1   = warp + 4;           // second tree

    // Lane's fixed slice of x: elements 4*(lane+32k)..+3, k=0..7 (32 floats).
    const float4* __restrict__ xg = (const float4*)(x + (size_t)row * DIM);
    float4 xr[8];
    #pragma unroll
    for (int k = 0; k < 8; ++k) xr[k] = __ldg(xg + lane + 32 * k);

    int cur0 = 0, cur1 = 0;              // node index within each tree

    float* __restrict__ act0 = g_act + (size_t)row * NACT + t0 * NSTEP;
    float* __restrict__ act1 = g_act + (size_t)row * NACT + t1 * NSTEP;

    #pragma unroll 1
    for (int step = 0; step < NSTEP; ++step) {
        const int w0 = t0 * NN + cur0;
        const int w1 = t1 * NN + cur1;
        const float4* __restrict__ Wr0 = (const float4*)(Win + (size_t)w0 * DIM);
        const float4* __restrict__ Wr1 = (const float4*)(Win + (size_t)w1 * DIM);

        float a0 = 0.f, b0 = 0.f;        // two partial accumulators per tree
        float a1 = 0.f, b1 = 0.f;
        #pragma unroll
        for (int k = 0; k < 8; ++k) {
            const float4 v0 = __ldg(Wr0 + lane + 32 * k);
            const float4 v1 = __ldg(Wr1 + lane + 32 * k);
            a0 += v0.x * xr[k].x + v0.y * xr[k].y;
            b0 += v0.z * xr[k].z + v0.w * xr[k].w;
            a1 += v1.x * xr[k].x + v1.y * xr[k].y;
            b1 += v1.z * xr[k].z + v1.w * xr[k].w;
        }
        float s0 = a0 + b0;
        float s1 = a1 + b1;
        #pragma unroll
        for (int off = 16; off; off >>= 1) {    // two interleaved butterflies
            s0 += __shfl_xor_sync(0xffffffffu, s0, off);
            s1 += __shfl_xor_sync(0xffffffffu, s1, off);
        }
        const float l0 = s0 + __ldg(bin + w0);
        const float l1 = s1 + __ldg(bin + w1);
        if (lane == 0) {
            act0[step] = l0 / (1.f + expf(-l0));   // silu
            act1[step] = l1 / (1.f + expf(-l1));
        }
        cur0 = 2 * cur0 + 1 + (l0 > 0.f ? 1 : 0);
        cur1 = 2 * cur1 + 1 + (l1 > 0.f ? 1 : 0);
    }

    if (lane == 0) {
        g_leaf[row * PAR + t0] = (cur0 - 1) >> 1;  // depth-7 node (127..254)
        g_leaf[row * PAR + t1] = (cur1 - 1) >> 1;
    }
}

// ---------------------------------------------------------------------------
// Kernel 3: stage 2 — out[row] = sum_i act_i * W_outT[node_i, :].
// fp16 weights, fp32 accumulate. 128 threads; thread t owns dims 8t..8t+7.
// Node indices reconstructed from the depth-7 leaf (path = prefixes of leaf).
// ---------------------------------------------------------------------------
__global__ __launch_bounds__(128) void fff_stage2(float* __restrict__ out)
{
    __shared__ float s_a[NACT];
    __shared__ int   s_w[NACT];

    const int row = blockIdx.x;
    const int tid = threadIdx.x;

    if (tid < NACT) {
        s_a[tid] = g_act[(size_t)row * NACT + tid];
        const int tree = tid >> 3;
        const int step = tid & 7;
        const int leaf = g_leaf[row * PAR + tree];      // heap idx at depth 7
        s_w[tid] = tree * NN + (((leaf + 1) >> (7 - step)) - 1);
    }
    __syncthreads();

    float acc[8];
    #pragma unroll
    for (int j = 0; j < 8; ++j) acc[j] = 0.f;

    #pragma unroll 8
    for (int i = 0; i < NACT; ++i) {
        const float a = s_a[i];
        const uint4 u = *((const uint4*)(g_WoutT_h + (size_t)s_w[i] * DIM) + tid);
        const __half2* h = (const __half2*)&u;
        #pragma unroll
        for (int j = 0; j < 4; ++j) {
            const float2 f = __half22float2(h[j]);
            acc[2 * j]     += a * f.x;
            acc[2 * j + 1] += a * f.y;
        }
    }

    float4* op = (float4*)(out + (size_t)row * DIM) + 2 * tid;
    float4 r0; r0.x = acc[0]; r0.y = acc[1]; r0.z = acc[2]; r0.w = acc[3];
    float4 r1; r1.x = acc[4]; r1.y = acc[5]; r1.z = acc[6]; r1.w = acc[7];
    op[0] = r0;
    op[1] = r1;
}

// ---------------------------------------------------------------------------
extern "C" void kernel_launch(void* const* d_in, const int* in_sizes, int n_in,
                              void* d_out, int out_size) {
    const float* oldx  = (const float*)d_in[0];   // [4,2048,1024] f32
    const float* W_in  = (const float*)d_in[1];   // [2040,1024] f32
    const float* b_in  = (const float*)d_in[2];   // [2040] f32
    const float* W_out = (const float*)d_in[3];   // [1024,2040] f32
    float* out = (float*)d_out;

    const int B = in_sizes[0] / DIM;              // 8192 rows

    transpose_wout<<<dim3((WIDTH + 31) / 32, DIM / 32), dim3(32, 8)>>>(W_out);
    fff_stage1<<<B, 128>>>(oldx, W_in, b_in);
    fff_stage2<<<B, 128>>>(out);
}